// round 13
// baseline (speedup 1.0000x reference)
#include <cuda_runtime.h>
#include <cuda_bf16.h>
#include <cstdint>

#define NV_MAX (512*512)
#define MAXE   (NV_MAX*8)
#define BIGV   1e10f
#define EPSV   1e-12f
#define MAXVAL 1000.0f
#define ITERS  100
#define NBINS  102          // dmin bins 0..101 (active<=100, halo==101)
#define NBLK   8
#define TPB    1024
#define SUCAP  1536         // phase-1 smem u capacity (slots)

// ---------------- global scratch ----------------
__device__ float  g_uA[NV_MAX];       // slot-indexed u ping-pong (A = parity 0)
__device__ float  g_uB[NV_MAX];

// slot-indexed tables
__device__ float4 g_e1[6 * NV_MAX];   // SR, SJ, SQRP(sqrt(qr-p^2), NaN if neg), A=p/qs
__device__ float4 g_e2[6 * NV_MAX];   // q, invq, j_slot(bits), k_slot(bits)
__device__ int    g_av[NV_MAX];       // slot -> vertex
__device__ float  g_sv[NV_MAX];       // slot -> seed val (BIGV if none)
__device__ int    g_pos[NV_MAX];      // vertex -> slot
__device__ int    g_dmin[NV_MAX];
__device__ int    g_bins[NBINS];
__device__ int    g_binstart[NBINS + 1];
__device__ int    g_cursor[NBINS];
__device__ int    g_box[4];           // rmin, rmax, cmin, cmax (expanded)

// fallback-path tables (R1)
__device__ float4 g_t4[MAXE];
__device__ float2 g_t2[MAXE];
__device__ int    g_pk[MAXE];

__device__ __forceinline__ float frcp(float x) {
    float y; asm("rcp.approx.f32 %0, %1;" : "=f"(y) : "f"(x)); return y;
}
__device__ __forceinline__ float fsqrt_ap(float x) {
    float y; asm("sqrt.approx.f32 %0, %1;" : "=f"(y) : "f"(x)); return y;
}
__device__ __forceinline__ float frsqrt_ap(float x) {
    float y; asm("rsqrt.approx.f32 %0, %1;" : "=f"(y) : "f"(x)); return y;
}
__device__ __forceinline__ void cluster_bar() {
    asm volatile("barrier.cluster.arrive.aligned;" ::: "memory");
    asm volatile("barrier.cluster.wait.aligned;"  ::: "memory");
}

// mesh graph distance: moves (+-1,0),(0,+-1),(+1,-1),(-1,+1)
__device__ __forceinline__ int mesh_dist(int dr, int dc) {
    int adr = abs(dr), adc = abs(dc);
    return ((long long)dr * (long long)dc >= 0) ? (adr + adc) : max(adr, adc);
}

// ================= fast path prologue =================

__global__ void kSeed(const int* __restrict__ ii, int n_init, int n)
{
    __shared__ int s_rmin, s_rmax, s_cmin, s_cmax;
    if (threadIdx.x == 0) { s_rmin = 0x7fffffff; s_rmax = -1; s_cmin = 0x7fffffff; s_cmax = -1; }
    __syncthreads();
    for (int i = threadIdx.x; i < n_init; i += blockDim.x) {
        int s = __ldg(ii + i);
        int r = s / n, c = s - r * n;
        atomicMin(&s_rmin, r); atomicMax(&s_rmax, r);
        atomicMin(&s_cmin, c); atomicMax(&s_cmax, c);
    }
    for (int i = threadIdx.x; i < NBINS; i += blockDim.x) { g_bins[i] = 0; g_cursor[i] = 0; }
    __syncthreads();
    if (threadIdx.x == 0) {
        g_box[0] = max(0, s_rmin - (ITERS + 1));
        g_box[1] = min(n - 1, s_rmax + (ITERS + 1));
        g_box[2] = max(0, s_cmin - (ITERS + 1));
        g_box[3] = min(n - 1, s_cmax + (ITERS + 1));
    }
}

__global__ void kA2(float* __restrict__ out,
                    const int* __restrict__ ii,
                    int n_init, int Nv, int n)
{
    const int stride = gridDim.x * blockDim.x;
    const int gtid = blockIdx.x * blockDim.x + threadIdx.x;
    for (int v = gtid; v < Nv; v += stride) out[v] = MAXVAL;

    const int r0 = g_box[0], r1 = g_box[1], c0 = g_box[2], c1 = g_box[3];
    const int bw = c1 - c0 + 1;
    const int btot = (r1 - r0 + 1) * bw;
    for (int idx = gtid; idx < btot; idx += stride) {
        int rr = idx / bw;
        int r = r0 + rr, c = c0 + (idx - rr * bw);
        int v = r * n + c;
        int dmin = 0x7fffffff;
        for (int i = 0; i < n_init; i++) {
            int s = __ldg(ii + i);
            int rs = s / n, cs = s - rs * n;
            dmin = min(dmin, mesh_dist(r - rs, c - cs));
        }
        g_dmin[v] = dmin;
        if (dmin < NBINS) atomicAdd(&g_bins[dmin], 1);
    }
}

__global__ void kB_scan()
{
    if (threadIdx.x == 0 && blockIdx.x == 0) {
        int acc = 0;
        for (int d = 0; d < NBINS; d++) { g_binstart[d] = acc; acc += g_bins[d]; }
        g_binstart[NBINS] = acc;
    }
}

__global__ void kC2(const int* __restrict__ ii,
                    const float* __restrict__ iv,
                    int n_init, int n)
{
    const int stride = gridDim.x * blockDim.x;
    const int gtid = blockIdx.x * blockDim.x + threadIdx.x;
    const int r0 = g_box[0], r1 = g_box[1], c0 = g_box[2], c1 = g_box[3];
    const int bw = c1 - c0 + 1;
    const int btot = (r1 - r0 + 1) * bw;
    for (int idx = gtid; idx < btot; idx += stride) {
        int rr = idx / bw;
        int r = r0 + rr, c = c0 + (idx - rr * bw);
        int v = r * n + c;
        int d = g_dmin[v];
        if (d >= NBINS) continue;
        int slot = g_binstart[d] + atomicAdd(&g_cursor[d], 1);
        g_av[slot] = v;
        g_pos[v] = slot;
        float sval = BIGV;
        for (int i = 0; i < n_init; i++)
            if (__ldg(ii + i) == v) sval = __ldg(iv + i);
        g_sv[slot] = sval;
    }
}

__global__ void kD2(const float* __restrict__ M,
                    const float* __restrict__ V,
                    const int* __restrict__ adj)
{
    const int NA100 = g_binstart[ITERS + 1];
    const int stride = gridDim.x * blockDim.x;
    for (int slot = blockIdx.x * blockDim.x + threadIdx.x; slot < NA100; slot += stride) {
        int v = __ldg(&g_av[slot]);
        float xv0 = V[2*v], xv1 = V[2*v+1];
        for (int e = 0; e < 6; e++) {
            const int* ent = adj + ((size_t)v * 6 + e) * 4;
            int j = ent[1], k = ent[2], s = ent[3];
            float4 e1, e2;
            if (s < 0) {
                e1 = make_float4(BIGV, BIGV, 0.0f, 0.0f);
                e2 = make_float4(-BIGV, 0.0f, __int_as_float(slot), __int_as_float(slot));
            } else {
                float xj0 = V[2*j], xj1 = V[2*j+1];
                float xk0 = V[2*k], xk1 = V[2*k+1];
                float a0 = xv0 - xk0, a1 = xv1 - xk1;
                float b0 = xj0 - xk0, b1 = xj1 - xk1;
                float m00 = M[4*s+0], m01 = M[4*s+1], m10 = M[4*s+2], m11 = M[4*s+3];
                float Ma0 = m00*a0 + m01*a1;
                float Ma1 = m10*a0 + m11*a1;
                float Mb0 = m00*b0 + m01*b1;
                float Mb1 = m10*b0 + m11*b1;
                float p = b0*Ma0 + b1*Ma1;
                float q = b0*Mb0 + b1*Mb1;
                float r = a0*Ma0 + a1*Ma1;
                float SR = sqrtf(fmaxf(r, EPSV));
                float SJ = sqrtf(fmaxf(r - 2.0f*p + q, EPSV));
                float SQRP = sqrtf(q*r - p*p);           // NaN if negative -> interior skipped
                float qs = (q > EPSV) ? q : 1.0f;
                float invq = 1.0f / qs;
                int js = g_pos[j], ks = g_pos[k];        // neighbors have dmin<=101 -> slots exist
                e1 = make_float4(SR, SJ, SQRP, p * invq);
                e2 = make_float4(q, invq, __int_as_float(js), __int_as_float(ks));
            }
            g_e1[e * NV_MAX + slot] = e1;
            g_e2[e * NV_MAX + slot] = e2;
        }
    }
}

// ===== main solver: phase-1 single-CTA smem sweeps, phase-2 8-CTA cluster ====
__global__ void __cluster_dims__(NBLK, 1, 1) __launch_bounds__(TPB, 1)
kMainC(float* __restrict__ out)
{
    __shared__ int s_cnt[NBINS + 1];
    __shared__ float su[2][SUCAP];        // phase-1 u ping-pong (CTA0 only)
    for (int i = threadIdx.x; i < NBINS + 1; i += TPB) s_cnt[i] = g_binstart[i];
    __syncthreads();
    const int NH    = s_cnt[NBINS];       // active + halo slot count
    const int NA100 = s_cnt[ITERS + 1];   // active (dmin <= 100)
    const int cta   = blockIdx.x;
    const int T     = NBLK * TPB;
    const int gtid  = cta * TPB + threadIdx.x;

    // init slot-indexed u (both buffers) — needed for phase-2 reads beyond flush
    for (int i = gtid; i < NH; i += T) {
        float sv = __ldg(&g_sv[i]);
        float val = (sv != BIGV) ? sv : MAXVAL;
        __stcg(&g_uA[i], val); __stcg(&g_uB[i], val);
    }

    if (NA100 <= T) {
        // itSplit: #iterations runnable by CTA0 alone (writes fit in first TPB slots,
        // reads fit in SUCAP). Predicate monotone in it -> prefix length. Cap at 99.
        int itSplit = 0;
        for (int it = 0; it < ITERS; it++) {
            if (s_cnt[it + 2] <= TPB && s_cnt[it + 3] <= SUCAP) itSplit++; else break;
        }
        if (itSplit > ITERS - 1) itSplit = ITERS - 1;

        // register tables, contiguous ownership: slot = cta*TPB + tid
        const int slot = cta * TPB + threadIdx.x;
        const bool own = (slot < NA100);
        float eSR[6], eSJ[6], eSQ[6], eA[6], eQ[6], eIQ[6];
        int   eJ[6], eK[6];
        float sval = BIGV;
        if (own) {
            sval = __ldg(&g_sv[slot]);
#pragma unroll
            for (int e = 0; e < 6; e++) {
                float4 t1 = __ldg(&g_e1[e * NV_MAX + slot]);
                float4 t2 = __ldg(&g_e2[e * NV_MAX + slot]);
                eSR[e] = t1.x; eSJ[e] = t1.y; eSQ[e] = t1.z; eA[e] = t1.w;
                eQ[e]  = t2.x; eIQ[e] = t2.y;
                eJ[e]  = __float_as_int(t2.z);
                eK[e]  = __float_as_int(t2.w);
            }
        }

        // ---------- phase 1: CTA0 only, u in smem ----------
        if (cta == 0) {
            const int tid = threadIdx.x;
            const int initN = (NH < SUCAP) ? NH : SUCAP;
            for (int i = tid; i < initN; i += TPB) {
                float sv = __ldg(&g_sv[i]);
                float val = (sv != BIGV) ? sv : MAXVAL;
                su[0][i] = val; su[1][i] = val;
            }
            __syncthreads();
            float best = MAXVAL;
            if (own && sval != BIGV) best = sval;
            if (own) best = su[0][slot];
#pragma unroll 1
            for (int it = 0; it < itSplit; it++) {
                const float* uin  = su[it & 1];
                float*       uout = su[(it + 1) & 1];
                if (own && slot < s_cnt[it + 2]) {
                    float Tj[6], Tk[6];
#pragma unroll
                    for (int e = 0; e < 6; e++) {
                        Tj[e] = uin[eJ[e]];
                        Tk[e] = uin[eK[e]];
                    }
#pragma unroll
                    for (int e = 0; e < 6; e++) {
                        float dT = Tj[e] - Tk[e];
                        best = fminf(best, Tk[e] + eSR[e]);
                        best = fminf(best, Tj[e] + eSJ[e]);
                        float denom = fmaf(-dT, dT, eQ[e]);
                        if (denom > EPSV) {
                            float sq = eSQ[e] * frsqrt_ap(denom);
                            float tB = dT * sq * eIQ[e];
                            float l1 = eA[e] - tB, l2 = eA[e] + tB;
                            float base = Tk[e] + sq;
                            if (l1 > 0.0f && l1 < 1.0f) best = fminf(best, fmaf(l1, dT, base));
                            if (l2 > 0.0f && l2 < 1.0f) best = fminf(best, fmaf(l2, dT, base));
                        }
                    }
                    if (sval != BIGV) best = sval;
                    uout[slot] = best;
                }
                __syncthreads();
            }
            // flush written prefix to the buffer phase-2 iteration itSplit reads
            float* gflush = (itSplit & 1) ? g_uB : g_uA;
            const float* sfin = su[itSplit & 1];
            for (int i = tid; i < s_cnt[itSplit + 1]; i += TPB)
                __stcg(&gflush[i], sfin[i]);
        }
        cluster_bar();     // handoff: u init + phase-1 flush visible cluster-wide

        // ---------- phase 2: all CTAs, HW cluster barrier per iteration ----------
        const float* uin0 = (itSplit & 1) ? g_uB : g_uA;
        float best = MAXVAL;
        if (own) best = __ldcg(&uin0[slot]);
#pragma unroll 1
        for (int it = itSplit; it < ITERS; it++) {
            const float* uin  = (it & 1) ? g_uB : g_uA;
            float*       uout = (it & 1) ? g_uA : g_uB;
            if (own && slot < s_cnt[it + 2]) {
                float Tj[6], Tk[6];
#pragma unroll
                for (int e = 0; e < 6; e++) {
                    Tj[e] = __ldcg(&uin[eJ[e]]);
                    Tk[e] = __ldcg(&uin[eK[e]]);
                }
#pragma unroll
                for (int e = 0; e < 6; e++) {
                    float dT = Tj[e] - Tk[e];
                    best = fminf(best, Tk[e] + eSR[e]);
                    best = fminf(best, Tj[e] + eSJ[e]);
                    float denom = fmaf(-dT, dT, eQ[e]);
                    if (denom > EPSV) {
                        float sq = eSQ[e] * frsqrt_ap(denom);
                        float tB = dT * sq * eIQ[e];
                        float l1 = eA[e] - tB, l2 = eA[e] + tB;
                        float base = Tk[e] + sq;
                        if (l1 > 0.0f && l1 < 1.0f) best = fminf(best, fmaf(l1, dT, base));
                        if (l2 > 0.0f && l2 < 1.0f) best = fminf(best, fmaf(l2, dT, base));
                    }
                }
                if (sval != BIGV) best = sval;
                __stcg(&uout[slot], best);
            }
            if (it < ITERS - 1) cluster_bar();
        }
        if (own) out[__ldg(&g_av[slot])] = best;
    } else {
        // ---- streamed path (NA100 > thread count) ----
        cluster_bar();
#pragma unroll 1
        for (int it = 0; it < ITERS; it++) {
            const float* uin  = (it & 1) ? g_uB : g_uA;
            float*       uout = (it & 1) ? g_uA : g_uB;
            const int NAt = s_cnt[it + 2];
            for (int i = gtid; i < NAt; i += T) {
                float bst = __ldcg(&uin[i]);
#pragma unroll
                for (int e = 0; e < 6; e++) {
                    float4 t1 = __ldg(&g_e1[e * NV_MAX + i]);
                    float4 t2 = __ldg(&g_e2[e * NV_MAX + i]);
                    float Tj = __ldcg(&uin[__float_as_int(t2.z)]);
                    float Tk = __ldcg(&uin[__float_as_int(t2.w)]);
                    float dT = Tj - Tk;
                    bst = fminf(bst, Tk + t1.x);
                    bst = fminf(bst, Tj + t1.y);
                    float denom = fmaf(-dT, dT, t2.x);
                    if (denom > EPSV) {
                        float sq = t1.z * frsqrt_ap(denom);
                        float tB = dT * sq * t2.y;
                        float l1 = t1.w - tB, l2 = t1.w + tB;
                        float base = Tk + sq;
                        if (l1 > 0.0f && l1 < 1.0f) bst = fminf(bst, fmaf(l1, dT, base));
                        if (l2 > 0.0f && l2 < 1.0f) bst = fminf(bst, fmaf(l2, dT, base));
                    }
                }
                float sv = __ldg(&g_sv[i]);
                if (sv != BIGV) bst = sv;
                __stcg(&uout[i], bst);
            }
            cluster_bar();
        }
        const float* fin = ((ITERS - 1) & 1) ? g_uA : g_uB;   // it=99 wrote g_uA
        for (int i = gtid; i < NA100; i += T)
            out[__ldg(&g_av[i])] = __ldcg(&fin[i]);
    }
}

// ================= fallback path (R1, known good) =================
__global__ void precompute_kernel(const float* __restrict__ M,
                                  const float* __restrict__ V,
                                  const int* __restrict__ adj,
                                  int Nv, int K)
{
    int idx = blockIdx.x * blockDim.x + threadIdx.x;
    if (idx >= Nv * K) return;
    int v = idx / K;
    int slot = idx - v * K;
    int outn = slot * Nv + v;
    const int* e = adj + (size_t)idx * 4;
    int j = e[1], k = e[2], s = e[3];
    if (s < 0) {
        g_t4[outn] = make_float4(-BIGV, 0.0f, 0.0f, 0.0f);
        g_t2[outn] = make_float2(BIGV, BIGV);
        g_pk[outn] = 0;
        return;
    }
    float xv0 = V[2*v], xv1 = V[2*v+1];
    float xj0 = V[2*j], xj1 = V[2*j+1];
    float xk0 = V[2*k], xk1 = V[2*k+1];
    float a0 = xv0 - xk0, a1 = xv1 - xk1;
    float b0 = xj0 - xk0, b1 = xj1 - xk1;
    float m00 = M[4*s+0], m01 = M[4*s+1], m10 = M[4*s+2], m11 = M[4*s+3];
    float Ma0 = m00*a0 + m01*a1;
    float Ma1 = m10*a0 + m11*a1;
    float Mb0 = m00*b0 + m01*b1;
    float Mb1 = m10*b0 + m11*b1;
    float p = b0*Ma0 + b1*Ma1;
    float q = b0*Mb0 + b1*Mb1;
    float r = a0*Ma0 + a1*Ma1;
    float SR = sqrtf(fmaxf(r, EPSV));
    float SJ = sqrtf(fmaxf(r - 2.0f*p + q, EPSV));
    float qs = (q > EPSV) ? q : 1.0f;
    float invq = 1.0f / qs;
    float QRP = q*r - p*p;
    g_t4[outn] = make_float4(q, QRP, p * invq, invq);
    g_t2[outn] = make_float2(SR, SJ);
    int dj = j - v, dk = k - v;
    g_pk[outn] = (dk << 16) | (dj & 0xffff);
}

__global__ void init_kernel(float* __restrict__ u,
                            const int* __restrict__ ii,
                            const float* __restrict__ iv,
                            int n_init, int Nv)
{
    int v = blockIdx.x * blockDim.x + threadIdx.x;
    if (v >= Nv) return;
    float val = MAXVAL;
    for (int i = 0; i < n_init; i++)
        if (ii[i] == v) val = iv[i];
    u[v] = val;
}

template<int KT>
__global__ void __launch_bounds__(256) sweep_kernel(const float* __restrict__ uin,
                                                    float* __restrict__ uout,
                                                    const int* __restrict__ ii,
                                                    const float* __restrict__ iv,
                                                    int n_init, int Nv, int Kdyn)
{
    int v = blockIdx.x * blockDim.x + threadIdx.x;
    if (v >= Nv) return;
    const int K = (KT > 0) ? KT : Kdyn;
    float best = uin[v];
#pragma unroll
    for (int s = 0; s < K; s++) {
        int e = s * Nv + v;
        int pk = g_pk[e];
        float4 t4 = g_t4[e];
        float2 t2 = g_t2[e];
        int dj = (int)(short)(pk & 0xffff);
        int dk = pk >> 16;
        float Tj = uin[v + dj];
        float Tk = uin[v + dk];
        float dT = Tj - Tk;
        best = fminf(best, Tk + t2.x);
        best = fminf(best, Tj + t2.y);
        float q = t4.x, QRP = t4.y, A = t4.z, Bq = t4.w;
        float denom = fmaf(-dT, dT, q);
        float ds = (fabsf(denom) > EPSV) ? denom : 1.0f;
        float rad = QRP * frcp(ds);
        if ((denom > EPSV) && (rad >= 0.0f)) {
            float sq = fsqrt_ap(rad);
            float tB = dT * sq * Bq;
            float l1 = A - tB, l2 = A + tB;
            float base = Tk + sq;
            if (l1 > 0.0f && l1 < 1.0f) best = fminf(best, fmaf(l1, dT, base));
            if (l2 > 0.0f && l2 < 1.0f) best = fminf(best, fmaf(l2, dT, base));
        }
    }
    for (int i = 0; i < n_init; i++)
        if (ii[i] == v) best = iv[i];
    uout[v] = best;
}

// ================= host =================
extern "C" void kernel_launch(void* const* d_in, const int* in_sizes, int n_in,
                              void* d_out, int out_size)
{
    const float* M   = (const float*)d_in[0];
    const float* V   = (const float*)d_in[1];
    const int*   adj = (const int*)d_in[2];
    const int*   ii  = (const int*)d_in[3];
    const float* iv  = (const float*)d_in[4];
    int n_init = in_sizes[3];
    int Nv = in_sizes[1] / 2;
    int K  = in_sizes[2] / (Nv * 4);
    float* out = (float*)d_out;

    // mesh-family guard: Nv = n*n grid mesh, K == 6
    int n = (int)(sqrtf((float)Nv) + 0.5f);
    bool useFast = (K == 6) && (n >= 2) && (n * n == Nv) && (Nv <= NV_MAX) &&
                   (n_init >= 1) && (n_init <= 1024);

    if (useFast) {
        kSeed<<<1, 256>>>(ii, n_init, n);
        kA2<<<512, 256>>>(out, ii, n_init, Nv, n);
        kB_scan<<<1, 32>>>();
        kC2<<<128, 256>>>(ii, iv, n_init, n);
        kD2<<<32, 256>>>(M, V, adj);
        kMainC<<<NBLK, TPB>>>(out);
        return;
    }

    // fallback: R1 multi-launch path
    float* ubuf = nullptr;
    cudaGetSymbolAddress((void**)&ubuf, g_uA);
    int tot = Nv * K;
    precompute_kernel<<<(tot + 255) / 256, 256>>>(M, V, adj, Nv, K);
    init_kernel<<<(Nv + 255) / 256, 256>>>(out, ii, iv, n_init, Nv);
    int blocks = (Nv + 255) / 256;
    for (int it = 0; it < ITERS; it++) {
        const float* uin = (it & 1) ? ubuf : out;
        float* uout      = (it & 1) ? out  : ubuf;
        if (K == 6)
            sweep_kernel<6><<<blocks, 256>>>(uin, uout, ii, iv, n_init, Nv, K);
        else
            sweep_kernel<0><<<blocks, 256>>>(uin, uout, ii, iv, n_init, Nv, K);
    }
}

// round 14
// speedup vs baseline: 1.4146x; 1.4146x over previous
#include <cuda_runtime.h>
#include <cuda_bf16.h>
#include <cstdint>

#define NV_MAX (512*512)
#define MAXE   (NV_MAX*8)
#define BIGV   1e10f
#define EPSV   1e-12f
#define MAXVAL 1000.0f
#define ITERS  100
#define NBINS  102          // dmin bins 0..101 (active<=100, halo==101)
#define NBLK   8
#define TPB    1024
#define SUCAP  1536         // phase-1 smem u capacity (slots)

// ---------------- global scratch ----------------
__device__ float  g_uA[NV_MAX];       // slot-indexed u ping-pong (A = parity 0)
__device__ float  g_uB[NV_MAX];

// slot-indexed tables
__device__ float4 g_e1[6 * NV_MAX];   // SR, SJ, SQRP(sqrt(qr-p^2), NaN if neg), A=p/qs
__device__ float4 g_e2[6 * NV_MAX];   // q, invq, j_slot(bits), k_slot(bits)
__device__ int    g_av[NV_MAX];       // slot -> vertex
__device__ float  g_sv[NV_MAX];       // slot -> seed val (BIGV if none)
__device__ int    g_pos[NV_MAX];      // vertex -> slot
__device__ int    g_dmin[NV_MAX];
__device__ int    g_bins[NBINS];
__device__ int    g_binstart[NBINS + 1];
__device__ int    g_cursor[NBINS];
__device__ int    g_box[4];           // rmin, rmax, cmin, cmax (expanded)

// fallback-path tables (R1)
__device__ float4 g_t4[MAXE];
__device__ float2 g_t2[MAXE];
__device__ int    g_pk[MAXE];

__device__ __forceinline__ float frcp(float x) {
    float y; asm("rcp.approx.f32 %0, %1;" : "=f"(y) : "f"(x)); return y;
}
__device__ __forceinline__ float fsqrt_ap(float x) {
    float y; asm("sqrt.approx.f32 %0, %1;" : "=f"(y) : "f"(x)); return y;
}
__device__ __forceinline__ float frsqrt_ap(float x) {
    float y; asm("rsqrt.approx.f32 %0, %1;" : "=f"(y) : "f"(x)); return y;
}
__device__ __forceinline__ void cluster_bar() {
    asm volatile("barrier.cluster.arrive.aligned;" ::: "memory");
    asm volatile("barrier.cluster.wait.aligned;"  ::: "memory");
}

// mesh graph distance: moves (+-1,0),(0,+-1),(+1,-1),(-1,+1)
__device__ __forceinline__ int mesh_dist(int dr, int dc) {
    int adr = abs(dr), adc = abs(dc);
    return ((long long)dr * (long long)dc >= 0) ? (adr + adc) : max(adr, adc);
}

// ================= fast path prologue =================

__global__ void kSeed(const int* __restrict__ ii, int n_init, int n)
{
    __shared__ int s_rmin, s_rmax, s_cmin, s_cmax;
    if (threadIdx.x == 0) { s_rmin = 0x7fffffff; s_rmax = -1; s_cmin = 0x7fffffff; s_cmax = -1; }
    __syncthreads();
    for (int i = threadIdx.x; i < n_init; i += blockDim.x) {
        int s = __ldg(ii + i);
        int r = s / n, c = s - r * n;
        atomicMin(&s_rmin, r); atomicMax(&s_rmax, r);
        atomicMin(&s_cmin, c); atomicMax(&s_cmax, c);
    }
    for (int i = threadIdx.x; i < NBINS; i += blockDim.x) { g_bins[i] = 0; g_cursor[i] = 0; }
    __syncthreads();
    if (threadIdx.x == 0) {
        g_box[0] = max(0, s_rmin - (ITERS + 1));
        g_box[1] = min(n - 1, s_rmax + (ITERS + 1));
        g_box[2] = max(0, s_cmin - (ITERS + 1));
        g_box[3] = min(n - 1, s_cmax + (ITERS + 1));
    }
}

__global__ void kA2(float* __restrict__ out,
                    const int* __restrict__ ii,
                    int n_init, int Nv, int n)
{
    const int stride = gridDim.x * blockDim.x;
    const int gtid = blockIdx.x * blockDim.x + threadIdx.x;
    for (int v = gtid; v < Nv; v += stride) out[v] = MAXVAL;

    const int r0 = g_box[0], r1 = g_box[1], c0 = g_box[2], c1 = g_box[3];
    const int bw = c1 - c0 + 1;
    const int btot = (r1 - r0 + 1) * bw;
    for (int idx = gtid; idx < btot; idx += stride) {
        int rr = idx / bw;
        int r = r0 + rr, c = c0 + (idx - rr * bw);
        int v = r * n + c;
        int dmin = 0x7fffffff;
        for (int i = 0; i < n_init; i++) {
            int s = __ldg(ii + i);
            int rs = s / n, cs = s - rs * n;
            dmin = min(dmin, mesh_dist(r - rs, c - cs));
        }
        g_dmin[v] = dmin;
        if (dmin < NBINS) atomicAdd(&g_bins[dmin], 1);
    }
}

__global__ void kB_scan()
{
    if (threadIdx.x == 0 && blockIdx.x == 0) {
        int acc = 0;
        for (int d = 0; d < NBINS; d++) { g_binstart[d] = acc; acc += g_bins[d]; }
        g_binstart[NBINS] = acc;
    }
}

__global__ void kC2(const int* __restrict__ ii,
                    const float* __restrict__ iv,
                    int n_init, int n)
{
    const int stride = gridDim.x * blockDim.x;
    const int gtid = blockIdx.x * blockDim.x + threadIdx.x;
    const int r0 = g_box[0], r1 = g_box[1], c0 = g_box[2], c1 = g_box[3];
    const int bw = c1 - c0 + 1;
    const int btot = (r1 - r0 + 1) * bw;
    for (int idx = gtid; idx < btot; idx += stride) {
        int rr = idx / bw;
        int r = r0 + rr, c = c0 + (idx - rr * bw);
        int v = r * n + c;
        int d = g_dmin[v];
        if (d >= NBINS) continue;
        int slot = g_binstart[d] + atomicAdd(&g_cursor[d], 1);
        g_av[slot] = v;
        g_pos[v] = slot;
        float sval = BIGV;
        for (int i = 0; i < n_init; i++)
            if (__ldg(ii + i) == v) sval = __ldg(iv + i);
        g_sv[slot] = sval;
    }
}

__global__ void kD2(const float* __restrict__ M,
                    const float* __restrict__ V,
                    const int* __restrict__ adj)
{
    const int NA100 = g_binstart[ITERS + 1];
    const int stride = gridDim.x * blockDim.x;
    for (int slot = blockIdx.x * blockDim.x + threadIdx.x; slot < NA100; slot += stride) {
        int v = __ldg(&g_av[slot]);
        float xv0 = V[2*v], xv1 = V[2*v+1];
        for (int e = 0; e < 6; e++) {
            const int* ent = adj + ((size_t)v * 6 + e) * 4;
            int j = ent[1], k = ent[2], s = ent[3];
            float4 e1, e2;
            if (s < 0) {
                e1 = make_float4(BIGV, BIGV, 0.0f, 0.0f);
                e2 = make_float4(-BIGV, 0.0f, __int_as_float(slot), __int_as_float(slot));
            } else {
                float xj0 = V[2*j], xj1 = V[2*j+1];
                float xk0 = V[2*k], xk1 = V[2*k+1];
                float a0 = xv0 - xk0, a1 = xv1 - xk1;
                float b0 = xj0 - xk0, b1 = xj1 - xk1;
                float m00 = M[4*s+0], m01 = M[4*s+1], m10 = M[4*s+2], m11 = M[4*s+3];
                float Ma0 = m00*a0 + m01*a1;
                float Ma1 = m10*a0 + m11*a1;
                float Mb0 = m00*b0 + m01*b1;
                float Mb1 = m10*b0 + m11*b1;
                float p = b0*Ma0 + b1*Ma1;
                float q = b0*Mb0 + b1*Mb1;
                float r = a0*Ma0 + a1*Ma1;
                float SR = sqrtf(fmaxf(r, EPSV));
                float SJ = sqrtf(fmaxf(r - 2.0f*p + q, EPSV));
                float SQRP = sqrtf(q*r - p*p);           // NaN if negative -> interior skipped
                float qs = (q > EPSV) ? q : 1.0f;
                float invq = 1.0f / qs;
                int js = g_pos[j], ks = g_pos[k];        // neighbors have dmin<=101 -> slots exist
                e1 = make_float4(SR, SJ, SQRP, p * invq);
                e2 = make_float4(q, invq, __int_as_float(js), __int_as_float(ks));
            }
            g_e1[e * NV_MAX + slot] = e1;
            g_e2[e * NV_MAX + slot] = e2;
        }
    }
}

// ===== main solver: phase-1 single-CTA smem, phase-2 warp-interleaved cluster =====
__global__ void __cluster_dims__(NBLK, 1, 1) __launch_bounds__(TPB, 1)
kMainC(float* __restrict__ out)
{
    __shared__ int s_cnt[NBINS + 1];
    __shared__ float su[2][SUCAP];        // phase-1 u ping-pong (CTA0 only)
    for (int i = threadIdx.x; i < NBINS + 1; i += TPB) s_cnt[i] = g_binstart[i];
    __syncthreads();
    const int NH    = s_cnt[NBINS];       // active + halo slot count
    const int NA100 = s_cnt[ITERS + 1];   // active (dmin <= 100)
    const int cta   = blockIdx.x;
    const int T     = NBLK * TPB;
    const int gtid  = cta * TPB + threadIdx.x;

    // init slot-indexed u (both buffers) — phase-2 reads beyond the flush need this
    for (int i = gtid; i < NH; i += T) {
        float sv = __ldg(&g_sv[i]);
        float val = (sv != BIGV) ? sv : MAXVAL;
        __stcg(&g_uA[i], val); __stcg(&g_uB[i], val);
    }

    if (NA100 <= T) {
        // itSplit: #iterations CTA0 can run alone (writes fit TPB, reads fit SUCAP)
        int itSplit = 0;
        for (int it = 0; it < ITERS; it++) {
            if (s_cnt[it + 2] <= TPB && s_cnt[it + 3] <= SUCAP) itSplit++; else break;
        }
        if (itSplit > ITERS - 1) itSplit = ITERS - 1;

        // ---------- phase 1: CTA0 only, contiguous slots, u in smem ----------
        if (cta == 0) {
            const int tid = threadIdx.x;
            const int slot1 = tid;                        // contiguous
            const bool own1 = (slot1 < NA100);
            float fSR[6], fSJ[6], fSQ[6], fA[6], fQ[6], fIQ[6];
            int   fJ[6], fK[6];
            float sval1 = BIGV;
            if (own1) {
                sval1 = __ldg(&g_sv[slot1]);
#pragma unroll
                for (int e = 0; e < 6; e++) {
                    float4 t1 = __ldg(&g_e1[e * NV_MAX + slot1]);
                    float4 t2 = __ldg(&g_e2[e * NV_MAX + slot1]);
                    fSR[e] = t1.x; fSJ[e] = t1.y; fSQ[e] = t1.z; fA[e] = t1.w;
                    fQ[e]  = t2.x; fIQ[e] = t2.y;
                    fJ[e]  = __float_as_int(t2.z);
                    fK[e]  = __float_as_int(t2.w);
                }
            }
            const int initN = (NH < SUCAP) ? NH : SUCAP;
            for (int i = tid; i < initN; i += TPB) {
                float sv = __ldg(&g_sv[i]);
                float val = (sv != BIGV) ? sv : MAXVAL;
                su[0][i] = val; su[1][i] = val;
            }
            __syncthreads();
            float best1 = own1 ? su[0][slot1] : MAXVAL;
#pragma unroll 1
            for (int it = 0; it < itSplit; it++) {
                const float* uin  = su[it & 1];
                float*       uout = su[(it + 1) & 1];
                if (own1 && slot1 < s_cnt[it + 2]) {
                    float Tj[6], Tk[6];
#pragma unroll
                    for (int e = 0; e < 6; e++) {
                        Tj[e] = uin[fJ[e]];
                        Tk[e] = uin[fK[e]];
                    }
#pragma unroll
                    for (int e = 0; e < 6; e++) {
                        float dT = Tj[e] - Tk[e];
                        best1 = fminf(best1, Tk[e] + fSR[e]);
                        best1 = fminf(best1, Tj[e] + fSJ[e]);
                        float denom = fmaf(-dT, dT, fQ[e]);
                        if (denom > EPSV) {
                            float sq = fSQ[e] * frsqrt_ap(denom);
                            float tB = dT * sq * fIQ[e];
                            float l1 = fA[e] - tB, l2 = fA[e] + tB;
                            float base = Tk[e] + sq;
                            if (l1 > 0.0f && l1 < 1.0f) best1 = fminf(best1, fmaf(l1, dT, base));
                            if (l2 > 0.0f && l2 < 1.0f) best1 = fminf(best1, fmaf(l2, dT, base));
                        }
                    }
                    if (sval1 != BIGV) best1 = sval1;
                    uout[slot1] = best1;
                }
                __syncthreads();
            }
            // flush written prefix to the buffer phase-2 iteration itSplit reads
            float* gflush = (itSplit & 1) ? g_uB : g_uA;
            const float* sfin = su[itSplit & 1];
            for (int i = tid; i < s_cnt[itSplit + 1]; i += TPB)
                __stcg(&gflush[i], sfin[i]);
        }
        cluster_bar();     // handoff: u init + phase-1 flush visible cluster-wide

        // ---------- phase 2: all CTAs, WARP-INTERLEAVED ownership (R10) ----------
        const int w = threadIdx.x >> 5, lane = threadIdx.x & 31;
        const int slot = ((w * NBLK + cta) << 5) + lane;
        const bool own = (slot < NA100);

        float eSR[6], eSJ[6], eSQ[6], eA[6], eQ[6], eIQ[6];
        int   eJ[6], eK[6];
        float best = MAXVAL, sval = BIGV;
        if (own) {
            sval = __ldg(&g_sv[slot]);
#pragma unroll
            for (int e = 0; e < 6; e++) {
                float4 t1 = __ldg(&g_e1[e * NV_MAX + slot]);
                float4 t2 = __ldg(&g_e2[e * NV_MAX + slot]);
                eSR[e] = t1.x; eSJ[e] = t1.y; eSQ[e] = t1.z; eA[e] = t1.w;
                eQ[e]  = t2.x; eIQ[e] = t2.y;
                eJ[e]  = __float_as_int(t2.z);
                eK[e]  = __float_as_int(t2.w);
            }
            const float* uin0 = (itSplit & 1) ? g_uB : g_uA;
            best = __ldcg(&uin0[slot]);
        }
#pragma unroll 1
        for (int it = itSplit; it < ITERS; it++) {
            const float* uin  = (it & 1) ? g_uB : g_uA;
            float*       uout = (it & 1) ? g_uA : g_uB;
            if (own && slot < s_cnt[it + 2]) {
                float Tj[6], Tk[6];
#pragma unroll
                for (int e = 0; e < 6; e++) {
                    Tj[e] = __ldcg(&uin[eJ[e]]);
                    Tk[e] = __ldcg(&uin[eK[e]]);
                }
#pragma unroll
                for (int e = 0; e < 6; e++) {
                    float dT = Tj[e] - Tk[e];
                    best = fminf(best, Tk[e] + eSR[e]);
                    best = fminf(best, Tj[e] + eSJ[e]);
                    float denom = fmaf(-dT, dT, eQ[e]);
                    if (denom > EPSV) {
                        float sq = eSQ[e] * frsqrt_ap(denom);
                        float tB = dT * sq * eIQ[e];
                        float l1 = eA[e] - tB, l2 = eA[e] + tB;
                        float base = Tk[e] + sq;
                        if (l1 > 0.0f && l1 < 1.0f) best = fminf(best, fmaf(l1, dT, base));
                        if (l2 > 0.0f && l2 < 1.0f) best = fminf(best, fmaf(l2, dT, base));
                    }
                }
                if (sval != BIGV) best = sval;
                __stcg(&uout[slot], best);
            }
            if (it < ITERS - 1) cluster_bar();
        }
        if (own) out[__ldg(&g_av[slot])] = best;
    } else {
        // ---- streamed path (NA100 > thread count) ----
        cluster_bar();
#pragma unroll 1
        for (int it = 0; it < ITERS; it++) {
            const float* uin  = (it & 1) ? g_uB : g_uA;
            float*       uout = (it & 1) ? g_uA : g_uB;
            const int NAt = s_cnt[it + 2];
            for (int i = gtid; i < NAt; i += T) {
                float bst = __ldcg(&uin[i]);
#pragma unroll
                for (int e = 0; e < 6; e++) {
                    float4 t1 = __ldg(&g_e1[e * NV_MAX + i]);
                    float4 t2 = __ldg(&g_e2[e * NV_MAX + i]);
                    float Tj = __ldcg(&uin[__float_as_int(t2.z)]);
                    float Tk = __ldcg(&uin[__float_as_int(t2.w)]);
                    float dT = Tj - Tk;
                    bst = fminf(bst, Tk + t1.x);
                    bst = fminf(bst, Tj + t1.y);
                    float denom = fmaf(-dT, dT, t2.x);
                    if (denom > EPSV) {
                        float sq = t1.z * frsqrt_ap(denom);
                        float tB = dT * sq * t2.y;
                        float l1 = t1.w - tB, l2 = t1.w + tB;
                        float base = Tk + sq;
                        if (l1 > 0.0f && l1 < 1.0f) bst = fminf(bst, fmaf(l1, dT, base));
                        if (l2 > 0.0f && l2 < 1.0f) bst = fminf(bst, fmaf(l2, dT, base));
                    }
                }
                float sv = __ldg(&g_sv[i]);
                if (sv != BIGV) bst = sv;
                __stcg(&uout[i], bst);
            }
            cluster_bar();
        }
        const float* fin = ((ITERS - 1) & 1) ? g_uA : g_uB;   // it=99 wrote g_uA
        for (int i = gtid; i < NA100; i += T)
            out[__ldg(&g_av[i])] = __ldcg(&fin[i]);
    }
}

// ================= fallback path (R1, known good) =================
__global__ void precompute_kernel(const float* __restrict__ M,
                                  const float* __restrict__ V,
                                  const int* __restrict__ adj,
                                  int Nv, int K)
{
    int idx = blockIdx.x * blockDim.x + threadIdx.x;
    if (idx >= Nv * K) return;
    int v = idx / K;
    int slot = idx - v * K;
    int outn = slot * Nv + v;
    const int* e = adj + (size_t)idx * 4;
    int j = e[1], k = e[2], s = e[3];
    if (s < 0) {
        g_t4[outn] = make_float4(-BIGV, 0.0f, 0.0f, 0.0f);
        g_t2[outn] = make_float2(BIGV, BIGV);
        g_pk[outn] = 0;
        return;
    }
    float xv0 = V[2*v], xv1 = V[2*v+1];
    float xj0 = V[2*j], xj1 = V[2*j+1];
    float xk0 = V[2*k], xk1 = V[2*k+1];
    float a0 = xv0 - xk0, a1 = xv1 - xk1;
    float b0 = xj0 - xk0, b1 = xj1 - xk1;
    float m00 = M[4*s+0], m01 = M[4*s+1], m10 = M[4*s+2], m11 = M[4*s+3];
    float Ma0 = m00*a0 + m01*a1;
    float Ma1 = m10*a0 + m11*a1;
    float Mb0 = m00*b0 + m01*b1;
    float Mb1 = m10*b0 + m11*b1;
    float p = b0*Ma0 + b1*Ma1;
    float q = b0*Mb0 + b1*Mb1;
    float r = a0*Ma0 + a1*Ma1;
    float SR = sqrtf(fmaxf(r, EPSV));
    float SJ = sqrtf(fmaxf(r - 2.0f*p + q, EPSV));
    float qs = (q > EPSV) ? q : 1.0f;
    float invq = 1.0f / qs;
    float QRP = q*r - p*p;
    g_t4[outn] = make_float4(q, QRP, p * invq, invq);
    g_t2[outn] = make_float2(SR, SJ);
    int dj = j - v, dk = k - v;
    g_pk[outn] = (dk << 16) | (dj & 0xffff);
}

__global__ void init_kernel(float* __restrict__ u,
                            const int* __restrict__ ii,
                            const float* __restrict__ iv,
                            int n_init, int Nv)
{
    int v = blockIdx.x * blockDim.x + threadIdx.x;
    if (v >= Nv) return;
    float val = MAXVAL;
    for (int i = 0; i < n_init; i++)
        if (ii[i] == v) val = iv[i];
    u[v] = val;
}

template<int KT>
__global__ void __launch_bounds__(256) sweep_kernel(const float* __restrict__ uin,
                                                    float* __restrict__ uout,
                                                    const int* __restrict__ ii,
                                                    const float* __restrict__ iv,
                                                    int n_init, int Nv, int Kdyn)
{
    int v = blockIdx.x * blockDim.x + threadIdx.x;
    if (v >= Nv) return;
    const int K = (KT > 0) ? KT : Kdyn;
    float best = uin[v];
#pragma unroll
    for (int s = 0; s < K; s++) {
        int e = s * Nv + v;
        int pk = g_pk[e];
        float4 t4 = g_t4[e];
        float2 t2 = g_t2[e];
        int dj = (int)(short)(pk & 0xffff);
        int dk = pk >> 16;
        float Tj = uin[v + dj];
        float Tk = uin[v + dk];
        float dT = Tj - Tk;
        best = fminf(best, Tk + t2.x);
        best = fminf(best, Tj + t2.y);
        float q = t4.x, QRP = t4.y, A = t4.z, Bq = t4.w;
        float denom = fmaf(-dT, dT, q);
        float ds = (fabsf(denom) > EPSV) ? denom : 1.0f;
        float rad = QRP * frcp(ds);
        if ((denom > EPSV) && (rad >= 0.0f)) {
            float sq = fsqrt_ap(rad);
            float tB = dT * sq * Bq;
            float l1 = A - tB, l2 = A + tB;
            float base = Tk + sq;
            if (l1 > 0.0f && l1 < 1.0f) best = fminf(best, fmaf(l1, dT, base));
            if (l2 > 0.0f && l2 < 1.0f) best = fminf(best, fmaf(l2, dT, base));
        }
    }
    for (int i = 0; i < n_init; i++)
        if (ii[i] == v) best = iv[i];
    uout[v] = best;
}

// ================= host =================
extern "C" void kernel_launch(void* const* d_in, const int* in_sizes, int n_in,
                              void* d_out, int out_size)
{
    const float* M   = (const float*)d_in[0];
    const float* V   = (const float*)d_in[1];
    const int*   adj = (const int*)d_in[2];
    const int*   ii  = (const int*)d_in[3];
    const float* iv  = (const float*)d_in[4];
    int n_init = in_sizes[3];
    int Nv = in_sizes[1] / 2;
    int K  = in_sizes[2] / (Nv * 4);
    float* out = (float*)d_out;

    // mesh-family guard: Nv = n*n grid mesh, K == 6
    int n = (int)(sqrtf((float)Nv) + 0.5f);
    bool useFast = (K == 6) && (n >= 2) && (n * n == Nv) && (Nv <= NV_MAX) &&
                   (n_init >= 1) && (n_init <= 1024);

    if (useFast) {
        kSeed<<<1, 256>>>(ii, n_init, n);
        kA2<<<512, 256>>>(out, ii, n_init, Nv, n);
        kB_scan<<<1, 32>>>();
        kC2<<<128, 256>>>(ii, iv, n_init, n);
        kD2<<<32, 256>>>(M, V, adj);
        kMainC<<<NBLK, TPB>>>(out);
        return;
    }

    // fallback: R1 multi-launch path
    float* ubuf = nullptr;
    cudaGetSymbolAddress((void**)&ubuf, g_uA);
    int tot = Nv * K;
    precompute_kernel<<<(tot + 255) / 256, 256>>>(M, V, adj, Nv, K);
    init_kernel<<<(Nv + 255) / 256, 256>>>(out, ii, iv, n_init, Nv);
    int blocks = (Nv + 255) / 256;
    for (int it = 0; it < ITERS; it++) {
        const float* uin = (it & 1) ? ubuf : out;
        float* uout      = (it & 1) ? out  : ubuf;
        if (K == 6)
            sweep_kernel<6><<<blocks, 256>>>(uin, uout, ii, iv, n_init, Nv, K);
        else
            sweep_kernel<0><<<blocks, 256>>>(uin, uout, ii, iv, n_init, Nv, K);
    }
}